// round 16
// baseline (speedup 1.0000x reference)
#include <cuda_runtime.h>
#include <math.h>

#define CM 64      // d_model
#define DI 128     // d_inner
#define DS 16      // d_state
#define NPIX 14400
#define HWD 120
#define LPIX 576
#define CLEN 144
#define NCHUNK 100   // NPIX / CLEN

typedef unsigned long long u64;
__device__ __forceinline__ u64 bcast2(float w){
    u64 r; asm("mov.b64 %0, {%1, %1};" : "=l"(r) : "f"(w)); return r;
}
__device__ __forceinline__ void ffma2(u64 &d, u64 a, u64 b){
    asm("fma.rn.f32x2 %0, %1, %2, %3;" : "=l"(d) : "l"(a), "l"(b), "l"(d));
}
__device__ __forceinline__ float2 unpack2(u64 v){
    float2 r; asm("mov.b64 {%0, %1}, %2;" : "=f"(r.x), "=f"(r.y) : "l"(v)); return r;
}

// ---------------- static scratch, slotted per branch ----------------
__device__ float g_xzT[2][2*2*DI*NPIX];   // [sl][dir][256][tok]
__device__ float g_u  [2][2*DI*NPIX];
__device__ float g_dl [2][2*DI*NPIX];
__device__ float g_Bmb[2][2*NPIX*DS];
__device__ float g_Cmb[2][2*NPIX*DS];
__device__ float g_gb0[2][DI*NPIX];
__device__ float g_gb1[2][DI*NPIX];
__device__ float g_cur[2][CM*NPIX];
__device__ float g_buf[2][CM*NPIX];
__device__ float g_P  [2][2*DI*DS*NCHUNK];
__device__ float g_He [2][2*DI*DS*NCHUNK];
__device__ float g_Hsb[2][2*DI*DS*NCHUNK];
__device__ float g_nf [4*CM*NPIX];
__device__ float g_t1 [2*CM*NPIX];
__device__ float g_t2 [CM*NPIX];
__device__ float g_hub1[2*CM];
__device__ float g_hub2[CM];
__device__ unsigned int g_cnt[8];

__device__ __forceinline__ int pixmap(int t){
    int sq = t/LPIX, l = t%LPIX;
    int nh = l/24, nw = l%24, pi = sq/5, pj = sq%5;
    return (nh*5+pi)*HWD + (nw*5+pj);
}

// ---------------- init: cur[0]=x, cur[1]=x^T ----------------
__global__ void k_init(const float* __restrict__ x)
{
    int p = blockIdx.x*blockDim.x + threadIdx.x;
    if (p >= NPIX) return;
    int c = blockIdx.y;
    int h = p/HWD, w = p%HWD;
    g_cur[0][(size_t)c*NPIX+p] = x[(size_t)c*NPIX+p];
    g_cur[1][(size_t)c*NPIX+p] = x[(size_t)c*NPIX + w*HWD + h];
}

// ---------- fused LayerNorm + gather + in-proj GEMM, slot-batched ------------
__global__ __launch_bounds__(256) void k_inproj(const float* __restrict__ imgb,
        const float* __restrict__ in_w_all,
        const float* __restrict__ lng_all, const float* __restrict__ lnb_all,
        int stage, int pixflag)
{
    __shared__ __align__(16) float Xs[64][64];
    __shared__ float Ws[128][33];
    __shared__ float ms[64], rs[64];
    int sl = blockIdx.z;
    int i = 2*sl + stage;
    const float* img = imgb + (size_t)sl*CM*NPIX;
    const float* W   = in_w_all + (size_t)i*2*2*DI*CM;
    const float* lng = lng_all + i*CM;
    const float* lnb = lnb_all + i*CM;
    float* C = g_xzT[sl];
    int t0 = blockIdx.x*64;
    int nb = blockIdx.y*128;
    int tid = threadIdx.x;
    int tg = tid & 15, eg = tid >> 4;

#pragma unroll
    for (int r=0;r<16;r++){
        int idx = tid + r*256;
        int kk = idx>>6, tt = idx&63;
        int t = t0+tt;
        int p = pixflag ? pixmap(t) : t;
        Xs[kk][tt] = img[(size_t)kk*NPIX + p];
    }
    __syncthreads();
    if (tid < 64){
        float s = 0.f;
#pragma unroll
        for (int k=0;k<64;k++) s += Xs[k][tid];
        float m = s*(1.f/64.f), v = 0.f;
#pragma unroll
        for (int k=0;k<64;k++){ float d = Xs[k][tid]-m; v += d*d; }
        ms[tid] = m;
        rs[tid] = rsqrtf(v*(1.f/64.f) + 1e-5f);
    }
    __syncthreads();
#pragma unroll
    for (int r=0;r<16;r++){
        int idx = tid + r*256;
        int kk = idx>>6, tt = idx&63;
        Xs[kk][tt] = (Xs[kk][tt]-ms[tt])*rs[tt]*lng[kk] + lnb[kk];
    }

    u64 acc2[8][2];
#pragma unroll
    for (int j=0;j<8;j++){ acc2[j][0]=0ull; acc2[j][1]=0ull; }
    for (int k0=0;k0<64;k0+=32){
        __syncthreads();
#pragma unroll
        for (int r=0;r<4;r++){
            int idx = tid + r*256;
            int e = idx>>3, kkb = (idx&7)*4;
            float4 v = *(const float4*)&W[(size_t)(nb+e)*CM + k0+kkb];
            Ws[e][kkb+0]=v.x; Ws[e][kkb+1]=v.y; Ws[e][kkb+2]=v.z; Ws[e][kkb+3]=v.w;
        }
        __syncthreads();
#pragma unroll 8
        for (int kk=0;kk<32;kk++){
            const u64* xp2 = (const u64*)&Xs[k0+kk][tg*4];
            u64 x01 = xp2[0], x23 = xp2[1];
#pragma unroll
            for (int j=0;j<8;j++){
                u64 w2 = bcast2(Ws[eg*8+j][kk]);
                ffma2(acc2[j][0], x01, w2);
                ffma2(acc2[j][1], x23, w2);
            }
        }
    }
#pragma unroll
    for (int j=0;j<8;j++){
        size_t row = (size_t)(nb + eg*8 + j)*NPIX;
        float2 a = unpack2(acc2[j][0]);
        float2 b = unpack2(acc2[j][1]);
        float4 o = make_float4(a.x, a.y, b.x, b.y);
        *(float4*)&C[row + t0 + tg*4] = o;
    }
}

// ---- fused conv+silu + xproj GEMM + dt/softplus + B/C pack, slot-batched ----
__global__ __launch_bounds__(256) void k_cxp(
    const float* __restrict__ conv_w_all, const float* __restrict__ conv_b_all,
    const float* __restrict__ xproj_all, const float* __restrict__ dt_w_all,
    const float* __restrict__ dt_b_all, int stage, int Lseq)
{
    __shared__ __align__(16) float Us[32][64];
    __shared__ float Ws[64][33];
    __shared__ float Cs[36][65];
    __shared__ float cws[DI*4];
    __shared__ float cbs[DI];
    __shared__ float dws[4][DI];
    __shared__ float dbs[DI];
    int dir = blockIdx.y;
    int sl = blockIdx.z;
    int i = 2*sl + stage;
    int t0 = blockIdx.x*64;
    int tid = threadIdx.x;
    int tg = tid & 15, eg = tid >> 4;
    {
        const float* cw = conv_w_all + ((size_t)i*2 + dir)*DI*4;
        const float* cb = conv_b_all + ((size_t)i*2 + dir)*DI;
        const float* dw = dt_w_all + ((size_t)i*2 + dir)*DI*4;
        const float* db = dt_b_all + ((size_t)i*2 + dir)*DI;
        for (int t=tid;t<DI*4;t+=256){ cws[t]=cw[t]; dws[t&3][t>>2]=dw[t]; }
        for (int t=tid;t<DI;t+=256){ cbs[t]=cb[t]; dbs[t]=db[t]; }
    }
    const float* xb = g_xzT[sl] + (size_t)dir*2*DI*NPIX;
    float* ub = g_u[sl] + (size_t)dir*DI*NPIX;
    const float* xp = xproj_all + ((size_t)i*2 + dir)*36*DI;

    u64 acc2[4][2];
#pragma unroll
    for (int j=0;j<4;j++){ acc2[j][0]=0ull; acc2[j][1]=0ull; }
    for (int k0=0;k0<DI;k0+=32){
        __syncthreads();
#pragma unroll
        for (int r=0;r<8;r++){
            int idx = tid + r*256;
            int kk = idx>>6, tt = idx&63;
            int ch = k0+kk;
            int tok = t0+tt;
            int l = tok % Lseq;
            const float* row = xb + (size_t)ch*NPIX;
            float a = cbs[ch];
            if (dir==0){
#pragma unroll
                for (int j=0;j<4;j++) if (l>=j) a += row[tok-j]*cws[ch*4+3-j];
            } else {
#pragma unroll
                for (int j=0;j<4;j++) if (l+j<Lseq) a += row[tok+j]*cws[ch*4+3-j];
            }
            float uu = a/(1.f+__expf(-a));
            Us[kk][tt] = uu;
            ub[(size_t)ch*NPIX + tok] = uu;
        }
#pragma unroll
        for (int r=0;r<2;r++){
            int idx = tid + r*256;
            int e = idx>>3, kkb = (idx&7)*4;
            float4 v = make_float4(0.f,0.f,0.f,0.f);
            if (e < 36) v = *(const float4*)&xp[(size_t)e*DI + k0+kkb];
            Ws[e][kkb+0]=v.x; Ws[e][kkb+1]=v.y; Ws[e][kkb+2]=v.z; Ws[e][kkb+3]=v.w;
        }
        __syncthreads();
#pragma unroll 8
        for (int kk=0;kk<32;kk++){
            const u64* xp2 = (const u64*)&Us[kk][tg*4];
            u64 x01 = xp2[0], x23 = xp2[1];
#pragma unroll
            for (int j=0;j<4;j++){
                u64 w2 = bcast2(Ws[eg*4+j][kk]);
                ffma2(acc2[j][0], x01, w2);
                ffma2(acc2[j][1], x23, w2);
            }
        }
    }
    __syncthreads();
#pragma unroll
    for (int j=0;j<4;j++){
        int n = eg*4 + j;
        if (n < 36){
            float2 a = unpack2(acc2[j][0]);
            float2 b = unpack2(acc2[j][1]);
            Cs[n][tg*4+0] = a.x; Cs[n][tg*4+1] = a.y;
            Cs[n][tg*4+2] = b.x; Cs[n][tg*4+3] = b.y;
        }
    }
    __syncthreads();
    int tokl = tid & 63;
    int kg = tid >> 6;
    int tok = t0 + tokl;
    float d0 = Cs[0][tokl], d1 = Cs[1][tokl], d2 = Cs[2][tokl], d3 = Cs[3][tokl];
    float* dlb = g_dl[sl] + (size_t)dir*DI*NPIX;
#pragma unroll 8
    for (int c=0;c<32;c++){
        int ch = kg*32 + c;
        float t = dbs[ch] + dws[0][ch]*d0 + dws[1][ch]*d1 + dws[2][ch]*d2 + dws[3][ch]*d3;
        t = (t>20.f)? t : log1pf(__expf(t));
        dlb[(size_t)ch*NPIX + tok] = t;
    }
    size_t bo = ((size_t)dir*NPIX + tok)*DS;
    if (kg < 2){
#pragma unroll
        for (int q=0;q<8;q++) g_Bmb[sl][bo + kg*8 + q] = Cs[4 + kg*8 + q][tokl];
    } else {
#pragma unroll
        for (int q=0;q<8;q++) g_Cmb[sl][bo + (kg-2)*8 + q] = Cs[20 + (kg-2)*8 + q][tokl];
    }
}

// --------- GEMM2 slot-batched, f32x2 inner loop ---------------------------
template<int TN>
__global__ __launch_bounds__(256) void k_gemm2(const float* __restrict__ X,
        const float* __restrict__ X2, const float* __restrict__ W,
        float* __restrict__ C, const float* __restrict__ base,
        const float* __restrict__ bias, const float* __restrict__ hub,
        int M, int K, int NW, int WS, int CS, int XS,
        size_t xss, size_t wss, size_t css, size_t bss,
        int rev, int mode, int xmode)
{
    constexpr int BN = 16*TN;
    __shared__ __align__(16) float Xs[32][64];
    __shared__ float Ws[BN][33];
    int sl = blockIdx.z;
    X += (size_t)sl*xss;
    if (X2) X2 += (size_t)sl*xss;
    W += (size_t)sl*wss;
    C += (size_t)sl*css;
    if (base) base += (size_t)sl*bss;
    int t0 = blockIdx.x*64;
    int wbase = blockIdx.y*WS;
    int cbase = blockIdx.y*CS;
    int xbase = blockIdx.y*XS;
    int tid = threadIdx.x;
    int tg = tid & 15, eg = tid >> 4;
    u64 acc2[TN][2];
#pragma unroll
    for (int j=0;j<TN;j++){ acc2[j][0]=0ull; acc2[j][1]=0ull; }
    for (int k0=0;k0<K;k0+=32){
        if (xmode == 0){
#pragma unroll
            for (int r=0;r<2;r++){
                int i = tid + r*256;
                int kk = i>>4, tt = (i&15)*4;
                size_t gidx = (size_t)(xbase+k0+kk)*M + t0+tt;
                float4 v = *(const float4*)&X[gidx];
                if (X2){
                    float4 w = *(const float4*)&X2[gidx];
                    v.x+=w.x; v.y+=w.y; v.z+=w.z; v.w+=w.w;
                }
                *(float4*)&Xs[kk][tt] = v;
            }
        } else {
#pragma unroll
            for (int r=0;r<8;r++){
                int i = tid + r*256;
                int kk = i>>6, tt = i&63;
                int ch = k0+kk;
                int t = t0+tt;
                float v = ((t&31)==0) ? hub[ch] : X[(size_t)ch*M + t];
                Xs[kk][tt] = fmaxf(v + bias[ch], 0.f);
            }
        }
#pragma unroll
        for (int r=0;r<BN/32;r++){
            int i = tid + r*256;
            int e = i>>3, kkb = (i&7)*4;
            float4 v = make_float4(0.f,0.f,0.f,0.f);
            if (e < NW) v = *(const float4*)&W[(size_t)(wbase+e)*K + k0+kkb];
            Ws[e][kkb+0]=v.x; Ws[e][kkb+1]=v.y; Ws[e][kkb+2]=v.z; Ws[e][kkb+3]=v.w;
        }
        __syncthreads();
#pragma unroll 8
        for (int kk=0;kk<32;kk++){
            const u64* xp2 = (const u64*)&Xs[kk][tg*4];
            u64 x01 = xp2[0], x23 = xp2[1];
#pragma unroll
            for (int j=0;j<TN;j++){
                u64 w2 = bcast2(Ws[eg*TN+j][kk]);
                ffma2(acc2[j][0], x01, w2);
                ffma2(acc2[j][1], x23, w2);
            }
        }
        __syncthreads();
    }
#pragma unroll
    for (int j=0;j<TN;j++){
        size_t row = (size_t)(cbase + eg*TN + j)*M;
        float2 pa = unpack2(acc2[j][0]);
        float2 pb = unpack2(acc2[j][1]);
        float a0 = pa.x, a1 = pa.y, a2 = pb.x, a3 = pb.y;
        if (mode == 0){
            if (!rev){
                float4 o = make_float4(a0,a1,a2,a3);
                *(float4*)&C[row + t0 + tg*4] = o;
            } else {
                C[row + (M-1-(t0+tg*4+0))] = a0;
                C[row + (M-1-(t0+tg*4+1))] = a1;
                C[row + (M-1-(t0+tg*4+2))] = a2;
                C[row + (M-1-(t0+tg*4+3))] = a3;
            }
        } else if (mode == 1){
            float av[4] = {a0,a1,a2,a3};
#pragma unroll
            for (int mj=0;mj<4;mj++){
                int p = pixmap(t0 + tg*4 + mj);
                C[row + p] = base[row + p] + av[mj];
            }
        } else {
            size_t i = row + t0 + tg*4;
            float4 b = *(const float4*)&base[i];
            float4 c = *(const float4*)&C[i];
            c.x += b.x + a0; c.y += b.y + a1;
            c.z += b.z + a2; c.w += b.w + a3;
            *(float4*)&C[i] = c;
        }
    }
}

// --------- stage-1 window out-proj, f32x2: cur+=..., nfx, nfy(rev) -----------
__global__ __launch_bounds__(256) void k_out3(const float* __restrict__ WaAll,
        const float* __restrict__ WbAll)
{
    __shared__ __align__(16) float Xs0[32][64];
    __shared__ __align__(16) float Xs1[32][64];
    __shared__ float Was[64][33];
    __shared__ float Wbs[64][33];
    int sl = blockIdx.y;
    int i = 2*sl + 1;
    const float* X0 = g_gb0[sl];
    const float* X1 = g_gb1[sl];
    const float* Wa = WaAll + (size_t)i*CM*DI;
    const float* Wb = WbAll + (size_t)i*CM*DI;
    float* cur = g_cur[sl];
    const float* buf = g_buf[sl];
    float* nfx = g_nf + (size_t)(2*sl)*CM*NPIX;
    float* nfy = g_nf + (size_t)(2*sl+1)*CM*NPIX;
    int t0 = blockIdx.x*64;
    int tid = threadIdx.x;
    int tg = tid & 15, eg = tid >> 4;
    u64 a1[4][2], a2[4][2], a3[4][2];
#pragma unroll
    for (int j=0;j<4;j++){
        a1[j][0]=0ull; a1[j][1]=0ull;
        a2[j][0]=0ull; a2[j][1]=0ull;
        a3[j][0]=0ull; a3[j][1]=0ull;
    }
    for (int k0=0;k0<DI;k0+=32){
#pragma unroll
        for (int r=0;r<2;r++){
            int idx = tid + r*256;
            int kk = idx>>4, tt = (idx&15)*4;
            size_t gidx = (size_t)(k0+kk)*NPIX + t0+tt;
            *(float4*)&Xs0[kk][tt] = *(const float4*)&X0[gidx];
            *(float4*)&Xs1[kk][tt] = *(const float4*)&X1[gidx];
        }
#pragma unroll
        for (int r=0;r<2;r++){
            int idx = tid + r*256;
            int e = idx>>3, kkb = (idx&7)*4;
            float4 va = *(const float4*)&Wa[(size_t)e*DI + k0+kkb];
            Was[e][kkb+0]=va.x; Was[e][kkb+1]=va.y; Was[e][kkb+2]=va.z; Was[e][kkb+3]=va.w;
            float4 vb = *(const float4*)&Wb[(size_t)e*DI + k0+kkb];
            Wbs[e][kkb+0]=vb.x; Wbs[e][kkb+1]=vb.y; Wbs[e][kkb+2]=vb.z; Wbs[e][kkb+3]=vb.w;
        }
        __syncthreads();
#pragma unroll 8
        for (int kk=0;kk<32;kk++){
            const u64* x0p = (const u64*)&Xs0[kk][tg*4];
            const u64* x1p = (const u64*)&Xs1[kk][tg*4];
            u64 x0a = x0p[0], x0b = x0p[1];
            u64 x1a = x1p[0], x1b = x1p[1];
#pragma unroll
            for (int j=0;j<4;j++){
                u64 wa2 = bcast2(Was[eg*4+j][kk]);
                u64 wb2 = bcast2(Wbs[eg*4+j][kk]);
                ffma2(a1[j][0], x0a, wa2); ffma2(a1[j][1], x0b, wa2);
                ffma2(a2[j][0], x1a, wa2); ffma2(a2[j][1], x1b, wa2);
                ffma2(a3[j][0], x1a, wb2); ffma2(a3[j][1], x1b, wb2);
            }
        }
        __syncthreads();
    }
#pragma unroll
    for (int j=0;j<4;j++){
        size_t row = (size_t)(eg*4+j)*NPIX;
        size_t i2 = row + t0 + tg*4;
        float2 p10 = unpack2(a1[j][0]), p11 = unpack2(a1[j][1]);
        float2 p20 = unpack2(a2[j][0]), p21 = unpack2(a2[j][1]);
        float2 p30 = unpack2(a3[j][0]), p31 = unpack2(a3[j][1]);
        float4 b = *(const float4*)&buf[i2];
        float4 c = *(const float4*)&cur[i2];
        c.x += b.x + p10.x + p20.x;
        c.y += b.y + p10.y + p20.y;
        c.z += b.z + p11.x + p21.x;
        c.w += b.w + p11.y + p21.y;
        *(float4*)&cur[i2] = c;
        float4 fx = make_float4(p10.x, p10.y, p11.x, p11.y);
        *(float4*)&nfx[i2] = fx;
        nfy[row + (NPIX-1-(t0+tg*4+0))] = p30.x;
        nfy[row + (NPIX-1-(t0+tg*4+1))] = p30.y;
        nfy[row + (NPIX-1-(t0+tg*4+2))] = p31.x;
        nfy[row + (NPIX-1-(t0+tg*4+3))] = p31.y;
    }
}

// ------------- chunked scan phase 1 + fused inter-chunk prefix ---------------
// P via exp(Aa * sum(dd)) — 1 FADD/step instead of 4 FMULs.
// Last block per (dgroup,dir|sl) column performs the c2 prefix inline.
__global__ void k_scan_c1(const float* __restrict__ Alog_all, int stage, int resetP)
{
    int z = blockIdx.z;
    int dir = z & 1, sl = z >> 1;
    int i = 2*sl + stage;
    int chunk = blockIdx.y;
    int l4 = threadIdx.x & 3;
    int d = blockIdx.x*64 + (threadIdx.x>>2);
    size_t abase = (((size_t)i*2+dir)*DI+d)*DS + l4*4;
    float Aa0 = -__expf(Alog_all[abase+0]);
    float Aa1 = -__expf(Alog_all[abase+1]);
    float Aa2 = -__expf(Alog_all[abase+2]);
    float Aa3 = -__expf(Alog_all[abase+3]);
    const float* dlp = g_dl[sl] + ((size_t)dir*DI+d)*NPIX;
    const float* up  = g_u [sl] + ((size_t)dir*DI+d)*NPIX;
    const float* Bp  = g_Bmb[sl] + (size_t)dir*NPIX*DS;
    float h0=0.f,h1=0.f,h2=0.f,h3=0.f;
    float S = 0.f;
    int s0 = chunk*CLEN;

    auto step = [&](float dd, float uu, int tok){
        float sc = dd*uu;
        float4 b4 = *(const float4*)&Bp[(size_t)tok*DS + l4*4];
        float a0 = __expf(dd*Aa0), a1 = __expf(dd*Aa1);
        float a2 = __expf(dd*Aa2), a3 = __expf(dd*Aa3);
        h0 = h0*a0 + sc*b4.x;
        h1 = h1*a1 + sc*b4.y;
        h2 = h2*a2 + sc*b4.z;
        h3 = h3*a3 + sc*b4.w;
        S += dd;
    };

    if (dir == 0){
        for (int tb=0; tb<CLEN; tb+=4){
            int tokb = s0 + tb;
            float4 dd4 = *(const float4*)&dlp[tokb];
            float4 uu4 = *(const float4*)&up[tokb];
            step(dd4.x, uu4.x, tokb+0);
            step(dd4.y, uu4.y, tokb+1);
            step(dd4.z, uu4.z, tokb+2);
            step(dd4.w, uu4.w, tokb+3);
        }
    } else {
        for (int tb=0; tb<CLEN; tb+=4){
            int tokb = NPIX-4-(s0+tb);
            float4 dd4 = *(const float4*)&dlp[tokb];
            float4 uu4 = *(const float4*)&up[tokb];
            step(dd4.w, uu4.w, tokb+3);
            step(dd4.z, uu4.z, tokb+2);
            step(dd4.y, uu4.y, tokb+1);
            step(dd4.x, uu4.x, tokb+0);
        }
    }
    size_t idx = (((size_t)dir*DI+d)*DS + l4*4)*NCHUNK + chunk;
    g_P[sl][idx+0*NCHUNK]=__expf(S*Aa0); g_He[sl][idx+0*NCHUNK]=h0;
    g_P[sl][idx+1*NCHUNK]=__expf(S*Aa1); g_He[sl][idx+1*NCHUNK]=h1;
    g_P[sl][idx+2*NCHUNK]=__expf(S*Aa2); g_He[sl][idx+2*NCHUNK]=h2;
    g_P[sl][idx+3*NCHUNK]=__expf(S*Aa3); g_He[sl][idx+3*NCHUNK]=h3;

    // ---- fused c2: last block of this (dgroup, dir|sl) column does prefix ----
    __threadfence();
    __shared__ unsigned int done;
    int cid = blockIdx.x + 2*blockIdx.z;   // 0..7
    if (threadIdx.x == 0) done = atomicAdd(&g_cnt[cid], 1u);
    __syncthreads();
    if (done == NCHUNK-1){
        if (threadIdx.x == 0) g_cnt[cid] = 0;   // reset for next launch (replay-safe)
        __threadfence();
        // 1024 chains (64 d x 16 states), 4 per thread
#pragma unroll
        for (int q=0;q<4;q++){
            int chain = threadIdx.x + 256*q;
            int dloc = chain >> 4, st = chain & 15;
            int dd2 = blockIdx.x*64 + dloc;
            size_t base = (((size_t)dir*DI + dd2)*DS + st)*NCHUNK;
            float h = 0.f;
            for (int c=0;c<NCHUNK;c++){
                if (resetP && (c % resetP) == 0) h = 0.f;
                g_Hsb[sl][base+c] = h;
                h = g_He[sl][base+c] + g_P[sl][base+c]*h;
            }
        }
    }
}

// phase 3: re-scan with carry-in + fused gate (time-vec x4, dir specialized)
__global__ void k_scan_c3(const float* __restrict__ Alog_all,
                          const float* __restrict__ D_all, int stage)
{
    int z = blockIdx.z;
    int dir = z & 1, sl = z >> 1;
    int i = 2*sl + stage;
    int chunk = blockIdx.y;
    int l4 = threadIdx.x & 3;
    int d = blockIdx.x*64 + (threadIdx.x>>2);
    size_t abase = (((size_t)i*2+dir)*DI+d)*DS + l4*4;
    float Aa0 = -__expf(Alog_all[abase+0]);
    float Aa1 = -__expf(Alog_all[abase+1]);
    float Aa2 = -__expf(Alog_all[abase+2]);
    float Aa3 = -__expf(Alog_all[abase+3]);
    float Dd = D_all[((size_t)i*2+dir)*DI+d];
    const float* dlp = g_dl[sl] + ((size_t)dir*DI+d)*NPIX;
    const float* up  = g_u [sl] + ((size_t)dir*DI+d)*NPIX;
    const float* Bp  = g_Bmb[sl] + (size_t)dir*NPIX*DS;
    const float* Cp  = g_Cmb[sl] + (size_t)dir*NPIX*DS;
    const float* zp  = g_xzT[sl] + (((size_t)dir*2+1)*DI+d)*NPIX;
    float* gp = (dir ? g_gb1[sl] : g_gb0[sl]) + (size_t)d*NPIX;
    size_t hidx = (((size_t)dir*DI+d)*DS + l4*4)*NCHUNK + chunk;
    float h0 = g_Hsb[sl][hidx+0*NCHUNK];
    float h1 = g_Hsb[sl][hidx+1*NCHUNK];
    float h2 = g_Hsb[sl][hidx+2*NCHUNK];
    float h3 = g_Hsb[sl][hidx+3*NCHUNK];
    int s0 = chunk*CLEN;

    auto step = [&](float dd, float uu, int tok) -> float {
        float sc = dd*uu;
        float4 b4 = *(const float4*)&Bp[(size_t)tok*DS + l4*4];
        h0 = h0*__expf(dd*Aa0) + sc*b4.x;
        h1 = h1*__expf(dd*Aa1) + sc*b4.y;
        h2 = h2*__expf(dd*Aa2) + sc*b4.z;
        h3 = h3*__expf(dd*Aa3) + sc*b4.w;
        float4 c4 = *(const float4*)&Cp[(size_t)tok*DS + l4*4];
        float cc = h0*c4.x + h1*c4.y + h2*c4.z + h3*c4.w;
        cc += __shfl_xor_sync(0xffffffffu, cc, 1);
        cc += __shfl_xor_sync(0xffffffffu, cc, 2);
        return cc;
    };

    if (dir == 0){
        for (int tb=0; tb<CLEN; tb+=4){
            int tokb = s0 + tb;
            float4 dd4 = *(const float4*)&dlp[tokb];
            float4 uu4 = *(const float4*)&up[tokb];
            float r0 = step(dd4.x, uu4.x, tokb+0);
            float r1 = step(dd4.y, uu4.y, tokb+1);
            float r2 = step(dd4.z, uu4.z, tokb+2);
            float r3 = step(dd4.w, uu4.w, tokb+3);
            if (l4 == 0){
                float4 zz4 = *(const float4*)&zp[tokb];
                float4 o;
                o.x = (r0 + uu4.x*Dd) * (zz4.x/(1.f+__expf(-zz4.x)));
                o.y = (r1 + uu4.y*Dd) * (zz4.y/(1.f+__expf(-zz4.y)));
                o.z = (r2 + uu4.z*Dd) * (zz4.z/(1.f+__expf(-zz4.z)));
                o.w = (r3 + uu4.w*Dd) * (zz4.w/(1.f+__expf(-zz4.w)));
                *(float4*)&gp[tokb] = o;
            }
        }
    } else {
        for (int tb=0; tb<CLEN; tb+=4){
            int tokb = NPIX-4-(s0+tb);
            float4 dd4 = *(const float4*)&dlp[tokb];
            float4 uu4 = *(const float4*)&up[tokb];
            float r3 = step(dd4.w, uu4.w, tokb+3);
            float r2 = step(dd4.z, uu4.z, tokb+2);
            float r1 = step(dd4.y, uu4.y, tokb+1);
            float r0 = step(dd4.x, uu4.x, tokb+0);
            if (l4 == 0){
                float4 zz4 = *(const float4*)&zp[tokb];
                float4 o;
                o.x = (r0 + uu4.x*Dd) * (zz4.x/(1.f+__expf(-zz4.x)));
                o.y = (r1 + uu4.y*Dd) * (zz4.y/(1.f+__expf(-zz4.y)));
                o.z = (r2 + uu4.z*Dd) * (zz4.z/(1.f+__expf(-zz4.z)));
                o.w = (r3 + uu4.w*Dd) * (zz4.w/(1.f+__expf(-zz4.w)));
                *(float4*)&gp[tokb] = o;
            }
        }
    }
}

// ---------------- GCN / final ----------------
__global__ void k_hubmean(const float* __restrict__ X, float* __restrict__ hub)
{
    int f = blockIdx.x;
    __shared__ float sm[256];
    float s = 0.f;
    for (int k=threadIdx.x;k<450;k+=256) s += X[(size_t)f*NPIX + k*32];
    sm[threadIdx.x]=s; __syncthreads();
    for (int st=128;st>0;st>>=1){
        if (threadIdx.x<st) sm[threadIdx.x]+=sm[threadIdx.x+st];
        __syncthreads();
    }
    if (threadIdx.x==0) hub[f]=sm[0]*(1.f/450.f);
}

__global__ void k_final(const float* __restrict__ x, const float* __restrict__ b2,
                        float* __restrict__ out)
{
    int p = blockIdx.x*blockDim.x + threadIdx.x;
    if (p >= NPIX) return;
    int c = blockIdx.y;
    int h = p/HWD, w = p%HWD;
    float g = ((p&31)==0 ? g_hub2[c] : g_t2[(size_t)c*NPIX+p]) + b2[c];
    out[(size_t)c*NPIX+p] = x[(size_t)c*NPIX+p] + g_cur[0][(size_t)c*NPIX+p]
        + g_cur[1][(size_t)c*NPIX + w*HWD + h] + g;
}

// ---------------- host driver ----------------
extern "C" void kernel_launch(void* const* d_in, const int* in_sizes, int n_in,
                              void* d_out, int out_size)
{
    const float* A[28];
    if (in_sizes[9] == 256){
        const int map[28] = {0,1,2,3,4,5,6,7,8, 11,12,13,14,15,16,17,18,
                             9,10, 19,20, 21,22,23,24,25,26,27};
        for (int k=0;k<28;k++) A[k]=(const float*)d_in[map[k]];
    } else {
        for (int k=0;k<28;k++) A[k]=(const float*)d_in[k];
    }
    const float* x = A[0];

    float *p_cur, *p_buf, *p_gb0, *p_gb1, *p_nf, *p_t1, *p_t2, *p_hub1, *p_hub2;
    cudaGetSymbolAddress((void**)&p_cur, g_cur);
    cudaGetSymbolAddress((void**)&p_buf, g_buf);
    cudaGetSymbolAddress((void**)&p_gb0, g_gb0);
    cudaGetSymbolAddress((void**)&p_gb1, g_gb1);
    cudaGetSymbolAddress((void**)&p_nf,  g_nf);
    cudaGetSymbolAddress((void**)&p_t1,  g_t1);
    cudaGetSymbolAddress((void**)&p_t2,  g_t2);
    cudaGetSymbolAddress((void**)&p_hub1, g_hub1);
    cudaGetSymbolAddress((void**)&p_hub2, g_hub2);

    const size_t SS = (size_t)CM*NPIX;
    const size_t GS = (size_t)DI*NPIX;
    const size_t WS2 = (size_t)2*CM*DI;

    k_init<<<dim3(113,CM),128>>>(x);

    for (int s=0; s<2; s++){
        // ---- pixel mamba; chunked scan, carry reset every 4 chunks (576/144)
        k_inproj<<<dim3(225,4,2),256>>>(p_cur, A[1], A[17], A[18], s, 1);
        k_cxp<<<dim3(225,2,2),256>>>(A[2], A[3], A[4], A[5], A[6], s, LPIX);
        k_scan_c1<<<dim3(2,NCHUNK,4),256>>>(A[7], s, LPIX/CLEN);
        k_scan_c3<<<dim3(2,NCHUNK,4),256>>>(A[7], A[8], s);
        // buf = cur + pixel residual (scatter)
        k_gemm2<4><<<dim3(225,1,2),256>>>(p_gb0, p_gb1, A[21] + (size_t)s*CM*DI,
                                          p_buf, p_cur, nullptr, nullptr,
                                          NPIX, DI, 64, 64, 64, 0,
                                          GS, WS2, SS, SS, 0, 1, 0);
        // ---- window mamba; chunked scan, no reset
        k_inproj<<<dim3(225,4,2),256>>>(p_buf, A[9], A[19], A[20], s, 0);
        k_cxp<<<dim3(225,2,2),256>>>(A[10], A[11], A[12], A[13], A[14], s, NPIX);
        k_scan_c1<<<dim3(2,NCHUNK,4),256>>>(A[15], s, 0);
        k_scan_c3<<<dim3(2,NCHUNK,4),256>>>(A[15], A[16], s);
        if (s == 1){
            k_out3<<<dim3(225,2),256>>>(A[22], A[23]);
        } else {
            k_gemm2<4><<<dim3(225,1,2),256>>>(p_gb0, p_gb1, A[22] + (size_t)s*CM*DI,
                                              p_cur, p_buf, nullptr, nullptr,
                                              NPIX, DI, 64, 64, 64, 0,
                                              GS, WS2, SS, SS, 0, 2, 0);
        }
    }

    // GCN: layer 1 (256 -> 128)
    k_gemm2<8><<<dim3(225,1,1),256>>>(p_nf, nullptr, A[24], p_t1, nullptr, nullptr, nullptr,
                                      NPIX, 4*CM, 128, 128, 128, 0,
                                      0, 0, 0, 0, 0, 0, 0);
    k_hubmean<<<2*CM,256>>>(p_t1, p_hub1);
    // layer 2 (128 -> 64) with fused hub-substitute + bias + relu
    k_gemm2<4><<<dim3(225,1,1),256>>>(p_t1, nullptr, A[26], p_t2, nullptr, A[25], p_hub1,
                                      NPIX, 2*CM, 64, 64, 64, 0,
                                      0, 0, 0, 0, 0, 0, 2);
    k_hubmean<<<CM,256>>>(p_t2, p_hub2);
    k_final<<<dim3(113,CM),128>>>(x, A[27], (float*)d_out);
}

// round 17
// speedup vs baseline: 1.1232x; 1.1232x over previous
#include <cuda_runtime.h>
#include <math.h>

#define CM 64      // d_model
#define DI 128     // d_inner
#define DS 16      // d_state
#define NPIX 14400
#define HWD 120
#define LPIX 576
#define CLEN 144
#define NCHUNK 100   // NPIX / CLEN

typedef unsigned long long u64;
__device__ __forceinline__ u64 bcast2(float w){
    u64 r; asm("mov.b64 %0, {%1, %1};" : "=l"(r) : "f"(w)); return r;
}
__device__ __forceinline__ void ffma2(u64 &d, u64 a, u64 b){
    asm("fma.rn.f32x2 %0, %1, %2, %3;" : "=l"(d) : "l"(a), "l"(b), "l"(d));
}
__device__ __forceinline__ float2 unpack2(u64 v){
    float2 r; asm("mov.b64 {%0, %1}, %2;" : "=f"(r.x), "=f"(r.y) : "l"(v)); return r;
}

// ---------------- static scratch, slotted per branch ----------------
__device__ float g_xzT[2][2*2*DI*NPIX];   // [sl][dir][256][tok]
__device__ float g_u  [2][2*DI*NPIX];
__device__ float g_dl [2][2*DI*NPIX];
__device__ float g_Bmb[2][2*NPIX*DS];
__device__ float g_Cmb[2][2*NPIX*DS];
__device__ float g_gb0[2][DI*NPIX];
__device__ float g_gb1[2][DI*NPIX];
__device__ float g_cur[2][CM*NPIX];
__device__ float g_buf[2][CM*NPIX];
__device__ float g_P  [2][2*DI*DS*NCHUNK];
__device__ float g_He [2][2*DI*DS*NCHUNK];
__device__ float g_Hsb[2][2*DI*DS*NCHUNK];
__device__ float g_nf [4*CM*NPIX];
__device__ float g_t1 [2*CM*NPIX];
__device__ float g_t2 [CM*NPIX];
__device__ float g_hub1[2*CM];
__device__ float g_hub2[CM];

__device__ __forceinline__ int pixmap(int t){
    int sq = t/LPIX, l = t%LPIX;
    int nh = l/24, nw = l%24, pi = sq/5, pj = sq%5;
    return (nh*5+pi)*HWD + (nw*5+pj);
}

// ---------------- init: cur[0]=x, cur[1]=x^T ----------------
__global__ void k_init(const float* __restrict__ x)
{
    int p = blockIdx.x*blockDim.x + threadIdx.x;
    if (p >= NPIX) return;
    int c = blockIdx.y;
    int h = p/HWD, w = p%HWD;
    g_cur[0][(size_t)c*NPIX+p] = x[(size_t)c*NPIX+p];
    g_cur[1][(size_t)c*NPIX+p] = x[(size_t)c*NPIX + w*HWD + h];
}

// ---------- fused LayerNorm + gather + in-proj GEMM, slot-batched ------------
__global__ __launch_bounds__(256) void k_inproj(const float* __restrict__ imgb,
        const float* __restrict__ in_w_all,
        const float* __restrict__ lng_all, const float* __restrict__ lnb_all,
        int stage, int pixflag)
{
    __shared__ __align__(16) float Xs[64][64];
    __shared__ float Ws[128][33];
    __shared__ float ms[64], rs[64];
    int sl = blockIdx.z;
    int i = 2*sl + stage;
    const float* img = imgb + (size_t)sl*CM*NPIX;
    const float* W   = in_w_all + (size_t)i*2*2*DI*CM;
    const float* lng = lng_all + i*CM;
    const float* lnb = lnb_all + i*CM;
    float* C = g_xzT[sl];
    int t0 = blockIdx.x*64;
    int nb = blockIdx.y*128;
    int tid = threadIdx.x;
    int tg = tid & 15, eg = tid >> 4;

#pragma unroll
    for (int r=0;r<16;r++){
        int idx = tid + r*256;
        int kk = idx>>6, tt = idx&63;
        int t = t0+tt;
        int p = pixflag ? pixmap(t) : t;
        Xs[kk][tt] = img[(size_t)kk*NPIX + p];
    }
    __syncthreads();
    if (tid < 64){
        float s = 0.f;
#pragma unroll
        for (int k=0;k<64;k++) s += Xs[k][tid];
        float m = s*(1.f/64.f), v = 0.f;
#pragma unroll
        for (int k=0;k<64;k++){ float d = Xs[k][tid]-m; v += d*d; }
        ms[tid] = m;
        rs[tid] = rsqrtf(v*(1.f/64.f) + 1e-5f);
    }
    __syncthreads();
#pragma unroll
    for (int r=0;r<16;r++){
        int idx = tid + r*256;
        int kk = idx>>6, tt = idx&63;
        Xs[kk][tt] = (Xs[kk][tt]-ms[tt])*rs[tt]*lng[kk] + lnb[kk];
    }

    u64 acc2[8][2];
#pragma unroll
    for (int j=0;j<8;j++){ acc2[j][0]=0ull; acc2[j][1]=0ull; }
    for (int k0=0;k0<64;k0+=32){
        __syncthreads();
#pragma unroll
        for (int r=0;r<4;r++){
            int idx = tid + r*256;
            int e = idx>>3, kkb = (idx&7)*4;
            float4 v = *(const float4*)&W[(size_t)(nb+e)*CM + k0+kkb];
            Ws[e][kkb+0]=v.x; Ws[e][kkb+1]=v.y; Ws[e][kkb+2]=v.z; Ws[e][kkb+3]=v.w;
        }
        __syncthreads();
#pragma unroll 8
        for (int kk=0;kk<32;kk++){
            const u64* xp2 = (const u64*)&Xs[k0+kk][tg*4];
            u64 x01 = xp2[0], x23 = xp2[1];
#pragma unroll
            for (int j=0;j<8;j++){
                u64 w2 = bcast2(Ws[eg*8+j][kk]);
                ffma2(acc2[j][0], x01, w2);
                ffma2(acc2[j][1], x23, w2);
            }
        }
    }
#pragma unroll
    for (int j=0;j<8;j++){
        size_t row = (size_t)(nb + eg*8 + j)*NPIX;
        float2 a = unpack2(acc2[j][0]);
        float2 b = unpack2(acc2[j][1]);
        float4 o = make_float4(a.x, a.y, b.x, b.y);
        *(float4*)&C[row + t0 + tg*4] = o;
    }
}

// ---- fused conv+silu + xproj GEMM + dt/softplus + B/C pack, slot-batched ----
__global__ __launch_bounds__(256) void k_cxp(
    const float* __restrict__ conv_w_all, const float* __restrict__ conv_b_all,
    const float* __restrict__ xproj_all, const float* __restrict__ dt_w_all,
    const float* __restrict__ dt_b_all, int stage, int Lseq)
{
    __shared__ __align__(16) float Us[32][64];
    __shared__ float Ws[64][33];
    __shared__ float Cs[36][65];
    __shared__ float cws[DI*4];
    __shared__ float cbs[DI];
    __shared__ float dws[4][DI];
    __shared__ float dbs[DI];
    int dir = blockIdx.y;
    int sl = blockIdx.z;
    int i = 2*sl + stage;
    int t0 = blockIdx.x*64;
    int tid = threadIdx.x;
    int tg = tid & 15, eg = tid >> 4;
    {
        const float* cw = conv_w_all + ((size_t)i*2 + dir)*DI*4;
        const float* cb = conv_b_all + ((size_t)i*2 + dir)*DI;
        const float* dw = dt_w_all + ((size_t)i*2 + dir)*DI*4;
        const float* db = dt_b_all + ((size_t)i*2 + dir)*DI;
        for (int t=tid;t<DI*4;t+=256){ cws[t]=cw[t]; dws[t&3][t>>2]=dw[t]; }
        for (int t=tid;t<DI;t+=256){ cbs[t]=cb[t]; dbs[t]=db[t]; }
    }
    const float* xb = g_xzT[sl] + (size_t)dir*2*DI*NPIX;
    float* ub = g_u[sl] + (size_t)dir*DI*NPIX;
    const float* xp = xproj_all + ((size_t)i*2 + dir)*36*DI;

    u64 acc2[4][2];
#pragma unroll
    for (int j=0;j<4;j++){ acc2[j][0]=0ull; acc2[j][1]=0ull; }
    for (int k0=0;k0<DI;k0+=32){
        __syncthreads();
#pragma unroll
        for (int r=0;r<8;r++){
            int idx = tid + r*256;
            int kk = idx>>6, tt = idx&63;
            int ch = k0+kk;
            int tok = t0+tt;
            int l = tok % Lseq;
            const float* row = xb + (size_t)ch*NPIX;
            float a = cbs[ch];
            if (dir==0){
#pragma unroll
                for (int j=0;j<4;j++) if (l>=j) a += row[tok-j]*cws[ch*4+3-j];
            } else {
#pragma unroll
                for (int j=0;j<4;j++) if (l+j<Lseq) a += row[tok+j]*cws[ch*4+3-j];
            }
            float uu = a/(1.f+__expf(-a));
            Us[kk][tt] = uu;
            ub[(size_t)ch*NPIX + tok] = uu;
        }
#pragma unroll
        for (int r=0;r<2;r++){
            int idx = tid + r*256;
            int e = idx>>3, kkb = (idx&7)*4;
            float4 v = make_float4(0.f,0.f,0.f,0.f);
            if (e < 36) v = *(const float4*)&xp[(size_t)e*DI + k0+kkb];
            Ws[e][kkb+0]=v.x; Ws[e][kkb+1]=v.y; Ws[e][kkb+2]=v.z; Ws[e][kkb+3]=v.w;
        }
        __syncthreads();
#pragma unroll 8
        for (int kk=0;kk<32;kk++){
            const u64* xp2 = (const u64*)&Us[kk][tg*4];
            u64 x01 = xp2[0], x23 = xp2[1];
#pragma unroll
            for (int j=0;j<4;j++){
                u64 w2 = bcast2(Ws[eg*4+j][kk]);
                ffma2(acc2[j][0], x01, w2);
                ffma2(acc2[j][1], x23, w2);
            }
        }
    }
    __syncthreads();
#pragma unroll
    for (int j=0;j<4;j++){
        int n = eg*4 + j;
        if (n < 36){
            float2 a = unpack2(acc2[j][0]);
            float2 b = unpack2(acc2[j][1]);
            Cs[n][tg*4+0] = a.x; Cs[n][tg*4+1] = a.y;
            Cs[n][tg*4+2] = b.x; Cs[n][tg*4+3] = b.y;
        }
    }
    __syncthreads();
    int tokl = tid & 63;
    int kg = tid >> 6;
    int tok = t0 + tokl;
    float d0 = Cs[0][tokl], d1 = Cs[1][tokl], d2 = Cs[2][tokl], d3 = Cs[3][tokl];
    float* dlb = g_dl[sl] + (size_t)dir*DI*NPIX;
#pragma unroll 8
    for (int c=0;c<32;c++){
        int ch = kg*32 + c;
        float t = dbs[ch] + dws[0][ch]*d0 + dws[1][ch]*d1 + dws[2][ch]*d2 + dws[3][ch]*d3;
        t = (t>20.f)? t : log1pf(__expf(t));
        dlb[(size_t)ch*NPIX + tok] = t;
    }
    size_t bo = ((size_t)dir*NPIX + tok)*DS;
    if (kg < 2){
#pragma unroll
        for (int q=0;q<8;q++) g_Bmb[sl][bo + kg*8 + q] = Cs[4 + kg*8 + q][tokl];
    } else {
#pragma unroll
        for (int q=0;q<8;q++) g_Cmb[sl][bo + (kg-2)*8 + q] = Cs[20 + (kg-2)*8 + q][tokl];
    }
}

// --------- GEMM2 slot-batched, f32x2 inner loop ---------------------------
template<int TN>
__global__ __launch_bounds__(256) void k_gemm2(const float* __restrict__ X,
        const float* __restrict__ X2, const float* __restrict__ W,
        float* __restrict__ C, const float* __restrict__ base,
        const float* __restrict__ bias, const float* __restrict__ hub,
        int M, int K, int NW, int WS, int CS, int XS,
        size_t xss, size_t wss, size_t css, size_t bss,
        int rev, int mode, int xmode)
{
    constexpr int BN = 16*TN;
    __shared__ __align__(16) float Xs[32][64];
    __shared__ float Ws[BN][33];
    int sl = blockIdx.z;
    X += (size_t)sl*xss;
    if (X2) X2 += (size_t)sl*xss;
    W += (size_t)sl*wss;
    C += (size_t)sl*css;
    if (base) base += (size_t)sl*bss;
    int t0 = blockIdx.x*64;
    int wbase = blockIdx.y*WS;
    int cbase = blockIdx.y*CS;
    int xbase = blockIdx.y*XS;
    int tid = threadIdx.x;
    int tg = tid & 15, eg = tid >> 4;
    u64 acc2[TN][2];
#pragma unroll
    for (int j=0;j<TN;j++){ acc2[j][0]=0ull; acc2[j][1]=0ull; }
    for (int k0=0;k0<K;k0+=32){
        if (xmode == 0){
#pragma unroll
            for (int r=0;r<2;r++){
                int i = tid + r*256;
                int kk = i>>4, tt = (i&15)*4;
                size_t gidx = (size_t)(xbase+k0+kk)*M + t0+tt;
                float4 v = *(const float4*)&X[gidx];
                if (X2){
                    float4 w = *(const float4*)&X2[gidx];
                    v.x+=w.x; v.y+=w.y; v.z+=w.z; v.w+=w.w;
                }
                *(float4*)&Xs[kk][tt] = v;
            }
        } else {
#pragma unroll
            for (int r=0;r<8;r++){
                int i = tid + r*256;
                int kk = i>>6, tt = i&63;
                int ch = k0+kk;
                int t = t0+tt;
                float v = ((t&31)==0) ? hub[ch] : X[(size_t)ch*M + t];
                Xs[kk][tt] = fmaxf(v + bias[ch], 0.f);
            }
        }
#pragma unroll
        for (int r=0;r<BN/32;r++){
            int i = tid + r*256;
            int e = i>>3, kkb = (i&7)*4;
            float4 v = make_float4(0.f,0.f,0.f,0.f);
            if (e < NW) v = *(const float4*)&W[(size_t)(wbase+e)*K + k0+kkb];
            Ws[e][kkb+0]=v.x; Ws[e][kkb+1]=v.y; Ws[e][kkb+2]=v.z; Ws[e][kkb+3]=v.w;
        }
        __syncthreads();
#pragma unroll 8
        for (int kk=0;kk<32;kk++){
            const u64* xp2 = (const u64*)&Xs[kk][tg*4];
            u64 x01 = xp2[0], x23 = xp2[1];
#pragma unroll
            for (int j=0;j<TN;j++){
                u64 w2 = bcast2(Ws[eg*TN+j][kk]);
                ffma2(acc2[j][0], x01, w2);
                ffma2(acc2[j][1], x23, w2);
            }
        }
        __syncthreads();
    }
#pragma unroll
    for (int j=0;j<TN;j++){
        size_t row = (size_t)(cbase + eg*TN + j)*M;
        float2 pa = unpack2(acc2[j][0]);
        float2 pb = unpack2(acc2[j][1]);
        float a0 = pa.x, a1 = pa.y, a2 = pb.x, a3 = pb.y;
        if (mode == 0){
            if (!rev){
                float4 o = make_float4(a0,a1,a2,a3);
                *(float4*)&C[row + t0 + tg*4] = o;
            } else {
                C[row + (M-1-(t0+tg*4+0))] = a0;
                C[row + (M-1-(t0+tg*4+1))] = a1;
                C[row + (M-1-(t0+tg*4+2))] = a2;
                C[row + (M-1-(t0+tg*4+3))] = a3;
            }
        } else if (mode == 1){
            float av[4] = {a0,a1,a2,a3};
#pragma unroll
            for (int mj=0;mj<4;mj++){
                int p = pixmap(t0 + tg*4 + mj);
                C[row + p] = base[row + p] + av[mj];
            }
        } else {
            size_t i = row + t0 + tg*4;
            float4 b = *(const float4*)&base[i];
            float4 c = *(const float4*)&C[i];
            c.x += b.x + a0; c.y += b.y + a1;
            c.z += b.z + a2; c.w += b.w + a3;
            *(float4*)&C[i] = c;
        }
    }
}

// --------- stage-1 window out-proj, f32x2: cur+=..., nfx, nfy(rev) -----------
__global__ __launch_bounds__(256) void k_out3(const float* __restrict__ WaAll,
        const float* __restrict__ WbAll)
{
    __shared__ __align__(16) float Xs0[32][64];
    __shared__ __align__(16) float Xs1[32][64];
    __shared__ float Was[64][33];
    __shared__ float Wbs[64][33];
    int sl = blockIdx.y;
    int i = 2*sl + 1;
    const float* X0 = g_gb0[sl];
    const float* X1 = g_gb1[sl];
    const float* Wa = WaAll + (size_t)i*CM*DI;
    const float* Wb = WbAll + (size_t)i*CM*DI;
    float* cur = g_cur[sl];
    const float* buf = g_buf[sl];
    float* nfx = g_nf + (size_t)(2*sl)*CM*NPIX;
    float* nfy = g_nf + (size_t)(2*sl+1)*CM*NPIX;
    int t0 = blockIdx.x*64;
    int tid = threadIdx.x;
    int tg = tid & 15, eg = tid >> 4;
    u64 a1[4][2], a2[4][2], a3[4][2];
#pragma unroll
    for (int j=0;j<4;j++){
        a1[j][0]=0ull; a1[j][1]=0ull;
        a2[j][0]=0ull; a2[j][1]=0ull;
        a3[j][0]=0ull; a3[j][1]=0ull;
    }
    for (int k0=0;k0<DI;k0+=32){
#pragma unroll
        for (int r=0;r<2;r++){
            int idx = tid + r*256;
            int kk = idx>>4, tt = (idx&15)*4;
            size_t gidx = (size_t)(k0+kk)*NPIX + t0+tt;
            *(float4*)&Xs0[kk][tt] = *(const float4*)&X0[gidx];
            *(float4*)&Xs1[kk][tt] = *(const float4*)&X1[gidx];
        }
#pragma unroll
        for (int r=0;r<2;r++){
            int idx = tid + r*256;
            int e = idx>>3, kkb = (idx&7)*4;
            float4 va = *(const float4*)&Wa[(size_t)e*DI + k0+kkb];
            Was[e][kkb+0]=va.x; Was[e][kkb+1]=va.y; Was[e][kkb+2]=va.z; Was[e][kkb+3]=va.w;
            float4 vb = *(const float4*)&Wb[(size_t)e*DI + k0+kkb];
            Wbs[e][kkb+0]=vb.x; Wbs[e][kkb+1]=vb.y; Wbs[e][kkb+2]=vb.z; Wbs[e][kkb+3]=vb.w;
        }
        __syncthreads();
#pragma unroll 8
        for (int kk=0;kk<32;kk++){
            const u64* x0p = (const u64*)&Xs0[kk][tg*4];
            const u64* x1p = (const u64*)&Xs1[kk][tg*4];
            u64 x0a = x0p[0], x0b = x0p[1];
            u64 x1a = x1p[0], x1b = x1p[1];
#pragma unroll
            for (int j=0;j<4;j++){
                u64 wa2 = bcast2(Was[eg*4+j][kk]);
                u64 wb2 = bcast2(Wbs[eg*4+j][kk]);
                ffma2(a1[j][0], x0a, wa2); ffma2(a1[j][1], x0b, wa2);
                ffma2(a2[j][0], x1a, wa2); ffma2(a2[j][1], x1b, wa2);
                ffma2(a3[j][0], x1a, wb2); ffma2(a3[j][1], x1b, wb2);
            }
        }
        __syncthreads();
    }
#pragma unroll
    for (int j=0;j<4;j++){
        size_t row = (size_t)(eg*4+j)*NPIX;
        size_t i2 = row + t0 + tg*4;
        float2 p10 = unpack2(a1[j][0]), p11 = unpack2(a1[j][1]);
        float2 p20 = unpack2(a2[j][0]), p21 = unpack2(a2[j][1]);
        float2 p30 = unpack2(a3[j][0]), p31 = unpack2(a3[j][1]);
        float4 b = *(const float4*)&buf[i2];
        float4 c = *(const float4*)&cur[i2];
        c.x += b.x + p10.x + p20.x;
        c.y += b.y + p10.y + p20.y;
        c.z += b.z + p11.x + p21.x;
        c.w += b.w + p11.y + p21.y;
        *(float4*)&cur[i2] = c;
        float4 fx = make_float4(p10.x, p10.y, p11.x, p11.y);
        *(float4*)&nfx[i2] = fx;
        nfy[row + (NPIX-1-(t0+tg*4+0))] = p30.x;
        nfy[row + (NPIX-1-(t0+tg*4+1))] = p30.y;
        nfy[row + (NPIX-1-(t0+tg*4+2))] = p31.x;
        nfy[row + (NPIX-1-(t0+tg*4+3))] = p31.y;
    }
}

// ------------- chunked scan phase 1 (P via exp(Aa*sum dd)) -------------------
__global__ void k_scan_c1(const float* __restrict__ Alog_all, int stage)
{
    int z = blockIdx.z;
    int dir = z & 1, sl = z >> 1;
    int i = 2*sl + stage;
    int chunk = blockIdx.y;
    int l4 = threadIdx.x & 3;
    int d = blockIdx.x*64 + (threadIdx.x>>2);
    size_t abase = (((size_t)i*2+dir)*DI+d)*DS + l4*4;
    float Aa0 = -__expf(Alog_all[abase+0]);
    float Aa1 = -__expf(Alog_all[abase+1]);
    float Aa2 = -__expf(Alog_all[abase+2]);
    float Aa3 = -__expf(Alog_all[abase+3]);
    const float* dlp = g_dl[sl] + ((size_t)dir*DI+d)*NPIX;
    const float* up  = g_u [sl] + ((size_t)dir*DI+d)*NPIX;
    const float* Bp  = g_Bmb[sl] + (size_t)dir*NPIX*DS;
    float h0=0.f,h1=0.f,h2=0.f,h3=0.f;
    float S = 0.f;
    int s0 = chunk*CLEN;

    auto step = [&](float dd, float uu, int tok){
        float sc = dd*uu;
        float4 b4 = *(const float4*)&Bp[(size_t)tok*DS + l4*4];
        float a0 = __expf(dd*Aa0), a1 = __expf(dd*Aa1);
        float a2 = __expf(dd*Aa2), a3 = __expf(dd*Aa3);
        h0 = h0*a0 + sc*b4.x;
        h1 = h1*a1 + sc*b4.y;
        h2 = h2*a2 + sc*b4.z;
        h3 = h3*a3 + sc*b4.w;
        S += dd;
    };

    if (dir == 0){
        for (int tb=0; tb<CLEN; tb+=4){
            int tokb = s0 + tb;
            float4 dd4 = *(const float4*)&dlp[tokb];
            float4 uu4 = *(const float4*)&up[tokb];
            step(dd4.x, uu4.x, tokb+0);
            step(dd4.y, uu4.y, tokb+1);
            step(dd4.z, uu4.z, tokb+2);
            step(dd4.w, uu4.w, tokb+3);
        }
    } else {
        for (int tb=0; tb<CLEN; tb+=4){
            int tokb = NPIX-4-(s0+tb);
            float4 dd4 = *(const float4*)&dlp[tokb];
            float4 uu4 = *(const float4*)&up[tokb];
            step(dd4.w, uu4.w, tokb+3);
            step(dd4.z, uu4.z, tokb+2);
            step(dd4.y, uu4.y, tokb+1);
            step(dd4.x, uu4.x, tokb+0);
        }
    }
    size_t idx = (((size_t)dir*DI+d)*DS + l4*4)*NCHUNK + chunk;
    g_P[sl][idx+0*NCHUNK]=__expf(S*Aa0); g_He[sl][idx+0*NCHUNK]=h0;
    g_P[sl][idx+1*NCHUNK]=__expf(S*Aa1); g_He[sl][idx+1*NCHUNK]=h1;
    g_P[sl][idx+2*NCHUNK]=__expf(S*Aa2); g_He[sl][idx+2*NCHUNK]=h2;
    g_P[sl][idx+3*NCHUNK]=__expf(S*Aa3); g_He[sl][idx+3*NCHUNK]=h3;
}

// phase 2: serial inter-chunk prefix; resetP = chunks per independent seq (0 = never)
__global__ void k_scan_c2(int resetP)
{
    int idx = blockIdx.x*blockDim.x + threadIdx.x;
    if (idx >= 2*2*DI*DS) return;
    int sl = idx >> 12;
    int inner = idx & 4095;
    size_t base = (size_t)inner*NCHUNK;
    float h = 0.f;
    for (int c=0;c<NCHUNK;c++){
        if (resetP && (c % resetP) == 0) h = 0.f;
        g_Hsb[sl][base+c] = h;
        h = g_He[sl][base+c] + g_P[sl][base+c]*h;
    }
}

// phase 3: re-scan with carry-in + fused gate (time-vec x4, dir specialized)
__global__ void k_scan_c3(const float* __restrict__ Alog_all,
                          const float* __restrict__ D_all, int stage)
{
    int z = blockIdx.z;
    int dir = z & 1, sl = z >> 1;
    int i = 2*sl + stage;
    int chunk = blockIdx.y;
    int l4 = threadIdx.x & 3;
    int d = blockIdx.x*64 + (threadIdx.x>>2);
    size_t abase = (((size_t)i*2+dir)*DI+d)*DS + l4*4;
    float Aa0 = -__expf(Alog_all[abase+0]);
    float Aa1 = -__expf(Alog_all[abase+1]);
    float Aa2 = -__expf(Alog_all[abase+2]);
    float Aa3 = -__expf(Alog_all[abase+3]);
    float Dd = D_all[((size_t)i*2+dir)*DI+d];
    const float* dlp = g_dl[sl] + ((size_t)dir*DI+d)*NPIX;
    const float* up  = g_u [sl] + ((size_t)dir*DI+d)*NPIX;
    const float* Bp  = g_Bmb[sl] + (size_t)dir*NPIX*DS;
    const float* Cp  = g_Cmb[sl] + (size_t)dir*NPIX*DS;
    const float* zp  = g_xzT[sl] + (((size_t)dir*2+1)*DI+d)*NPIX;
    float* gp = (dir ? g_gb1[sl] : g_gb0[sl]) + (size_t)d*NPIX;
    size_t hidx = (((size_t)dir*DI+d)*DS + l4*4)*NCHUNK + chunk;
    float h0 = g_Hsb[sl][hidx+0*NCHUNK];
    float h1 = g_Hsb[sl][hidx+1*NCHUNK];
    float h2 = g_Hsb[sl][hidx+2*NCHUNK];
    float h3 = g_Hsb[sl][hidx+3*NCHUNK];
    int s0 = chunk*CLEN;

    auto step = [&](float dd, float uu, int tok) -> float {
        float sc = dd*uu;
        float4 b4 = *(const float4*)&Bp[(size_t)tok*DS + l4*4];
        h0 = h0*__expf(dd*Aa0) + sc*b4.x;
        h1 = h1*__expf(dd*Aa1) + sc*b4.y;
        h2 = h2*__expf(dd*Aa2) + sc*b4.z;
        h3 = h3*__expf(dd*Aa3) + sc*b4.w;
        float4 c4 = *(const float4*)&Cp[(size_t)tok*DS + l4*4];
        float cc = h0*c4.x + h1*c4.y + h2*c4.z + h3*c4.w;
        cc += __shfl_xor_sync(0xffffffffu, cc, 1);
        cc += __shfl_xor_sync(0xffffffffu, cc, 2);
        return cc;
    };

    if (dir == 0){
        for (int tb=0; tb<CLEN; tb+=4){
            int tokb = s0 + tb;
            float4 dd4 = *(const float4*)&dlp[tokb];
            float4 uu4 = *(const float4*)&up[tokb];
            float r0 = step(dd4.x, uu4.x, tokb+0);
            float r1 = step(dd4.y, uu4.y, tokb+1);
            float r2 = step(dd4.z, uu4.z, tokb+2);
            float r3 = step(dd4.w, uu4.w, tokb+3);
            if (l4 == 0){
                float4 zz4 = *(const float4*)&zp[tokb];
                float4 o;
                o.x = (r0 + uu4.x*Dd) * (zz4.x/(1.f+__expf(-zz4.x)));
                o.y = (r1 + uu4.y*Dd) * (zz4.y/(1.f+__expf(-zz4.y)));
                o.z = (r2 + uu4.z*Dd) * (zz4.z/(1.f+__expf(-zz4.z)));
                o.w = (r3 + uu4.w*Dd) * (zz4.w/(1.f+__expf(-zz4.w)));
                *(float4*)&gp[tokb] = o;
            }
        }
    } else {
        for (int tb=0; tb<CLEN; tb+=4){
            int tokb = NPIX-4-(s0+tb);
            float4 dd4 = *(const float4*)&dlp[tokb];
            float4 uu4 = *(const float4*)&up[tokb];
            float r3 = step(dd4.w, uu4.w, tokb+3);
            float r2 = step(dd4.z, uu4.z, tokb+2);
            float r1 = step(dd4.y, uu4.y, tokb+1);
            float r0 = step(dd4.x, uu4.x, tokb+0);
            if (l4 == 0){
                float4 zz4 = *(const float4*)&zp[tokb];
                float4 o;
                o.x = (r0 + uu4.x*Dd) * (zz4.x/(1.f+__expf(-zz4.x)));
                o.y = (r1 + uu4.y*Dd) * (zz4.y/(1.f+__expf(-zz4.y)));
                o.z = (r2 + uu4.z*Dd) * (zz4.z/(1.f+__expf(-zz4.z)));
                o.w = (r3 + uu4.w*Dd) * (zz4.w/(1.f+__expf(-zz4.w)));
                *(float4*)&gp[tokb] = o;
            }
        }
    }
}

// ---------------- GCN / final ----------------
__global__ void k_hubmean(const float* __restrict__ X, float* __restrict__ hub)
{
    int f = blockIdx.x;
    __shared__ float sm[256];
    float s = 0.f;
    for (int k=threadIdx.x;k<450;k+=256) s += X[(size_t)f*NPIX + k*32];
    sm[threadIdx.x]=s; __syncthreads();
    for (int st=128;st>0;st>>=1){
        if (threadIdx.x<st) sm[threadIdx.x]+=sm[threadIdx.x+st];
        __syncthreads();
    }
    if (threadIdx.x==0) hub[f]=sm[0]*(1.f/450.f);
}

__global__ void k_final(const float* __restrict__ x, const float* __restrict__ b2,
                        float* __restrict__ out)
{
    int p = blockIdx.x*blockDim.x + threadIdx.x;
    if (p >= NPIX) return;
    int c = blockIdx.y;
    int h = p/HWD, w = p%HWD;
    float g = ((p&31)==0 ? g_hub2[c] : g_t2[(size_t)c*NPIX+p]) + b2[c];
    out[(size_t)c*NPIX+p] = x[(size_t)c*NPIX+p] + g_cur[0][(size_t)c*NPIX+p]
        + g_cur[1][(size_t)c*NPIX + w*HWD + h] + g;
}

// ---------------- host driver ----------------
extern "C" void kernel_launch(void* const* d_in, const int* in_sizes, int n_in,
                              void* d_out, int out_size)
{
    const float* A[28];
    if (in_sizes[9] == 256){
        const int map[28] = {0,1,2,3,4,5,6,7,8, 11,12,13,14,15,16,17,18,
                             9,10, 19,20, 21,22,23,24,25,26,27};
        for (int k=0;k<28;k++) A[k]=(const float*)d_in[map[k]];
    } else {
        for (int k=0;k<28;k++) A[k]=(const float*)d_in[k];
    }
    const float* x = A[0];

    float *p_cur, *p_buf, *p_gb0, *p_gb1, *p_nf, *p_t1, *p_t2, *p_hub1, *p_hub2;
    cudaGetSymbolAddress((void**)&p_cur, g_cur);
    cudaGetSymbolAddress((void**)&p_buf, g_buf);
    cudaGetSymbolAddress((void**)&p_gb0, g_gb0);
    cudaGetSymbolAddress((void**)&p_gb1, g_gb1);
    cudaGetSymbolAddress((void**)&p_nf,  g_nf);
    cudaGetSymbolAddress((void**)&p_t1,  g_t1);
    cudaGetSymbolAddress((void**)&p_t2,  g_t2);
    cudaGetSymbolAddress((void**)&p_hub1, g_hub1);
    cudaGetSymbolAddress((void**)&p_hub2, g_hub2);

    const size_t SS = (size_t)CM*NPIX;
    const size_t GS = (size_t)DI*NPIX;
    const size_t WS2 = (size_t)2*CM*DI;

    k_init<<<dim3(113,CM),128>>>(x);

    for (int s=0; s<2; s++){
        // ---- pixel mamba; chunked scan, carry reset every 4 chunks (576/144)
        k_inproj<<<dim3(225,4,2),256>>>(p_cur, A[1], A[17], A[18], s, 1);
        k_cxp<<<dim3(225,2,2),256>>>(A[2], A[3], A[4], A[5], A[6], s, LPIX);
        k_scan_c1<<<dim3(2,NCHUNK,4),256>>>(A[7], s);
        k_scan_c2<<<8,1024>>>(LPIX/CLEN);
        k_scan_c3<<<dim3(2,NCHUNK,4),256>>>(A[7], A[8], s);
        // buf = cur + pixel residual (scatter)
        k_gemm2<4><<<dim3(225,1,2),256>>>(p_gb0, p_gb1, A[21] + (size_t)s*CM*DI,
                                          p_buf, p_cur, nullptr, nullptr,
                                          NPIX, DI, 64, 64, 64, 0,
                                          GS, WS2, SS, SS, 0, 1, 0);
        // ---- window mamba; chunked scan, no reset
        k_inproj<<<dim3(225,4,2),256>>>(p_buf, A[9], A[19], A[20], s, 0);
        k_cxp<<<dim3(225,2,2),256>>>(A[10], A[11], A[12], A[13], A[14], s, NPIX);
        k_scan_c1<<<dim3(2,NCHUNK,4),256>>>(A[15], s);
        k_scan_c2<<<8,1024>>>(0);
        k_scan_c3<<<dim3(2,NCHUNK,4),256>>>(A[15], A[16], s);
        if (s == 1){
            k_out3<<<dim3(225,2),256>>>(A[22], A[23]);
        } else {
            k_gemm2<4><<<dim3(225,1,2),256>>>(p_gb0, p_gb1, A[22] + (size_t)s*CM*DI,
                                              p_cur, p_buf, nullptr, nullptr,
                                              NPIX, DI, 64, 64, 64, 0,
                                              GS, WS2, SS, SS, 0, 2, 0);
        }
    }

    // GCN: layer 1 (256 -> 128)
    k_gemm2<8><<<dim3(225,1,1),256>>>(p_nf, nullptr, A[24], p_t1, nullptr, nullptr, nullptr,
                                      NPIX, 4*CM, 128, 128, 128, 0,
                                      0, 0, 0, 0, 0, 0, 0);
    k_hubmean<<<2*CM,256>>>(p_t1, p_hub1);
    // layer 2 (128 -> 64) with fused hub-substitute + bias + relu
    k_gemm2<4><<<dim3(225,1,1),256>>>(p_t1, nullptr, A[26], p_t2, nullptr, A[25], p_hub1,
                                      NPIX, 2*CM, 64, 64, 64, 0,
                                      0, 0, 0, 0, 0, 0, 2);
    k_hubmean<<<CM,256>>>(p_t2, p_hub2);
    k_final<<<dim3(113,CM),128>>>(x, A[27], (float*)d_out);
}